// round 15
// baseline (speedup 1.0000x reference)
#include <cuda_runtime.h>
#include <cstdint>

// ---------------- problem constants ----------------
#define C 96                 // feature channels (d = h = 96)
#define NMAX 65536
#define EMAX 1048576
#define WPAD 100             // padded k-stride for transposed W in smem
#define SW_FLOATS (C * WPAD) // 9600 floats = 38.4 KB

// ---------------- device scratch (no allocations allowed) ----------------
// NOTE: d_deg relies on static zero-init for the FIRST call; every call
// re-zeroes it during the fill phase for the next graph replay.
__device__ int   d_deg[NMAX];
__device__ int   d_rowptr[NMAX];       // tile-LOCAL exclusive scan
__device__ int   d_cursor[NMAX];       // tile-LOCAL fill cursor (post-fill: local end)
__device__ int   d_bsum[1024];         // per-tile degree totals
__device__ int   d_boff[1024];         // per-tile global offsets
__device__ int2  d_csr[EMAX];          // (src*C, weight-bits)
__device__ float d_dinv[NMAX];
__device__ float d_h1[(size_t)NMAX * C];
__device__ float d_xgcn[(size_t)NMAX * C];
__device__ float d_g[(size_t)NMAX * C];

// grid-barrier state (monotonic generation; survives across graph replays)
__device__ unsigned          d_barcnt = 0;
__device__ volatile unsigned d_bargen = 0;
__device__ unsigned          d_p2done = 0;   // last-block ticket for mid-scan

// ---------------- helpers ----------------
__device__ __forceinline__ float fsigmoid(float x) {
    return 1.0f / (1.0f + __expf(-x));
}
__device__ __forceinline__ float ftanh(float x) {
    return 1.0f - 2.0f / (__expf(2.0f * x) + 1.0f);
}
__device__ __forceinline__ int load_idx(const void* ei, int idx, int is64) {
    if (is64) return (int)((const long long*)ei)[idx];
    return ((const int*)ei)[idx];
}

__device__ __forceinline__ uint32_t f2tf32(float f) {
    uint32_t r;
    asm("cvt.rna.tf32.f32 %0, %1;" : "=r"(r) : "f"(f));
    return r;
}

// D += A(16x8 tf32) * B(8x8 tf32), fp32 accumulate. Row-major A, col-major B.
__device__ __forceinline__ void mma_tf32(
    float* c, uint32_t a0, uint32_t a1, uint32_t a2, uint32_t a3,
    uint32_t b0, uint32_t b1)
{
    asm volatile(
        "mma.sync.aligned.m16n8k8.row.col.f32.tf32.tf32.f32 "
        "{%0,%1,%2,%3}, {%4,%5,%6,%7}, {%8,%9}, {%0,%1,%2,%3};"
        : "+f"(c[0]), "+f"(c[1]), "+f"(c[2]), "+f"(c[3])
        : "r"(a0), "r"(a1), "r"(a2), "r"(a3), "r"(b0), "r"(b1));
}

// Software grid barrier (all blocks co-resident; grid sized via occupancy API).
__device__ __forceinline__ void grid_barrier() {
    __threadfence();
    __syncthreads();
    if (threadIdx.x == 0) {
        unsigned g = d_bargen;
        unsigned t = atomicAdd(&d_barcnt, 1u);
        if (t == gridDim.x - 1) {
            atomicExch(&d_barcnt, 0u);
            __threadfence();
            d_bargen = g + 1;
        } else {
            while (d_bargen == g) __nanosleep(64);
        }
    }
    __syncthreads();
    __threadfence();
}

// ---------------- GEMM phase v9: 16x32 warp tasks (load-balanced) ---------
// out[N,96] = A[N,K] @ W[K,96]; K in 96-row segments. Per segment, W is
// tf32-rounded ONCE while staging into smem TRANSPOSED, pad stride 100
// (bank map (4n+k)%32 all-distinct -> conflict-free B-fragment loads).
// Single-MMA (no A compensation): measured rel_err 4.2e-5 (24x margin).
// Warp task = 16 rows x 32 cols (4 n-tiles, acc[4][4]=16 regs).
// ntask = rowtiles*3 = 9375 over 4864 warps -> 1.93 tasks/warp: ceil is
// still 2 but each task is 48 (not 72) MMA-steps -> slowest-warp work per
// seg-pass drops 144 -> 96 steps (the R14 16x48 tiling idled ~36% of warps).
// Segment 1 accumulates via out +=.
template <int MODE>
__device__ void gemm_phase(
    const float* __restrict__ A0, const float* __restrict__ A1,
    const float* __restrict__ A2, const float* __restrict__ W,
    float* __restrict__ outp, int N, float* sWt)
{
    const int NSEG = (MODE == 0) ? 1 : 2;
    const int tid  = threadIdx.x;
    const int lane = tid & 31;
    const int wid  = tid >> 5;
    const int gwarp = blockIdx.x * 8 + wid;
    const int nwarp = gridDim.x * 8;
    const int rowtiles = (N + 15) >> 4;
    const int ntask = rowtiles * 3;          // x3 column thirds (32 cols each)

    const int lg = lane >> 2;                // 0..7
    const int kl = lane & 3;                 // 0..3

    for (int seg = 0; seg < NSEG; seg++) {
        __syncthreads();                      // prior users of sWt done
        const float* wseg = W + (size_t)seg * C * C;
        for (int i = tid; i < C * C; i += 256) {
            int k = i / C, n = i - k * C;     // i = k*96+n (coalesced gmem read)
            sWt[n * WPAD + k] = __uint_as_float(f2tf32(wseg[i]));
        }
        __syncthreads();

        const float* Asrc = (seg == 0) ? A0 : A1;

        for (int task = gwarp; task < ntask; task += nwarp) {
            const int rt    = task / 3;
            const int third = task - rt * 3;
            const int r0 = rt * 16 + lg;
            const int r1 = r0 + 8;
            const bool v0 = r0 < N;
            const bool v1 = r1 < N;
            const float* __restrict__ arow0 = Asrc + (size_t)r0 * C;
            const float* __restrict__ arow1 = Asrc + (size_t)r1 * C;

            float acc[4][4];
            #pragma unroll
            for (int nt = 0; nt < 4; nt++)
                #pragma unroll
                for (int q = 0; q < 4; q++) acc[nt][q] = 0.0f;

            #pragma unroll 2
            for (int ks = 0; ks < 12; ks++) {
                const int k0 = ks * 8;
                float a0 = v0 ? arow0[k0 + kl]     : 0.0f;
                float a1 = v1 ? arow1[k0 + kl]     : 0.0f;
                float a2 = v0 ? arow0[k0 + 4 + kl] : 0.0f;
                float a3 = v1 ? arow1[k0 + 4 + kl] : 0.0f;
                if (MODE == 2 && seg == 1) {
                    if (v0) {
                        a0 *= A2[(size_t)r0 * C + k0 + kl];
                        a2 *= A2[(size_t)r0 * C + k0 + 4 + kl];
                    }
                    if (v1) {
                        a1 *= A2[(size_t)r1 * C + k0 + kl];
                        a3 *= A2[(size_t)r1 * C + k0 + 4 + kl];
                    }
                }
                uint32_t h0 = f2tf32(a0), h1 = f2tf32(a1);
                uint32_t h2 = f2tf32(a2), h3 = f2tf32(a3);

                const float* wb = sWt + (size_t)(third * 32 + lg) * WPAD + k0 + kl;
                #pragma unroll
                for (int nt = 0; nt < 4; nt++) {
                    uint32_t b0 = __float_as_uint(wb[(size_t)nt * 8 * WPAD]);
                    uint32_t b1 = __float_as_uint(wb[(size_t)nt * 8 * WPAD + 4]);
                    mma_tf32(acc[nt], h0, h1, h2, h3, b0, b1);
                }
            }

            // store: d0,d1 -> (r0, cc..cc+1); d2,d3 -> (r1, cc..cc+1)
            const int cc = (lane & 3) * 2;
            #pragma unroll
            for (int nt = 0; nt < 4; nt++) {
                const int n0 = third * 32 + nt * 8 + cc;
                if (v0) {
                    float2* p = (float2*)(outp + (size_t)r0 * C + n0);
                    if (seg == 0) {
                        *p = make_float2(acc[nt][0], acc[nt][1]);
                    } else {
                        float2 o = *p;
                        *p = make_float2(o.x + acc[nt][0], o.y + acc[nt][1]);
                    }
                }
                if (v1) {
                    float2* p = (float2*)(outp + (size_t)r1 * C + n0);
                    if (seg == 0) {
                        *p = make_float2(acc[nt][2], acc[nt][3]);
                    } else {
                        float2 o = *p;
                        *p = make_float2(o.x + acc[nt][2], o.y + acc[nt][3]);
                    }
                }
            }
        }
    }
}

// ---------------- aggregation phase ----------------
// task = (node, channel-third); lane owns channel third*32+lane.
// CSR stores src*C premultiplied -> no IMAD in the inner loop.
// jbeg = local rowptr + tile offset; jend from post-fill cursor (== rowptr+deg).
template <int MODE>
__device__ void agg_phase(
    const float* __restrict__ H, const float* __restrict__ bias,
    const float* __restrict__ G, const float* __restrict__ HP,
    float* __restrict__ outp, int N, int2* sCS)
{
    const int wid  = threadIdx.x >> 5;
    const int lane = threadIdx.x & 31;
    int2* cs = &sCS[wid * 32];
    const int ntask = 3 * N;

    for (int task = blockIdx.x * 8 + wid; task < ntask; task += gridDim.x * 8) {
        const int n     = task / 3;
        const int third = task - n * 3;
        const int c     = third * 32 + lane;

        float dn = d_dinv[n];
        float a  = bias[c] + dn * dn * H[(size_t)n * C + c];

        const int boff = d_boff[n >> 8];
        const int jbeg = d_rowptr[n] + boff;
        const int jend = d_cursor[n] + boff;

        for (int base = jbeg; base < jend; base += 32) {
            int cnt = jend - base;
            if (cnt > 32) cnt = 32;
            if (lane < cnt) cs[lane] = d_csr[base + lane];
            __syncwarp();
            int t = 0;
            for (; t + 8 <= cnt; t += 8) {
                float xv[8], wv[8];
                #pragma unroll
                for (int q = 0; q < 8; q++) {
                    int2 e = cs[t + q];
                    wv[q] = __int_as_float(e.y);
                    xv[q] = H[(size_t)(e.x + c)];
                }
                #pragma unroll
                for (int q = 0; q < 8; q++) a += wv[q] * xv[q];
            }
            for (; t < cnt; t++) {
                int2 e = cs[t];
                a += __int_as_float(e.y) * H[(size_t)(e.x + c)];
            }
            __syncwarp();
        }

        const size_t o = (size_t)n * C + c;
        if (MODE == 0) {
            outp[o] = a;
        } else if (MODE == 1) {
            outp[o] = fsigmoid(a);
        } else {
            float u = G[o];
            outp[o] = u * HP[o] + (1.0f - u) * ftanh(a);
        }
    }
}

// ---------------- the megakernel (7 grid barriers) ----------------
__global__ void __launch_bounds__(256, 4) mega_kernel(
    const float* __restrict__ x, const void* __restrict__ ei,
    const float* __restrict__ h_prev,
    const float* __restrict__ Wx,  const float* __restrict__ bx,
    const float* __restrict__ Wuh, const float* __restrict__ buh,
    const float* __restrict__ Wch, const float* __restrict__ bch,
    float* __restrict__ out, int N, int E)
{
    extern __shared__ float sWt[];                // [SW_FLOATS] (38.4 KB)
    int2* sCS = (int2*)(sWt + SW_FLOATS);         // [8*32] int2 (2 KB)
    int*  sSc = (int*)sCS;                        // scan scratch (aliased)
    __shared__ int sIs64;

    const int tid  = threadIdx.x;
    const int NB   = gridDim.x;
    const int gtid = blockIdx.x * 256 + tid;
    const int nthr = NB * 256;
    const int lane = tid & 31;
    const int wid  = tid >> 5;

    // ---- Phase A: block-local dtype detect + histogram + gemm<0> ----
    {
        int lim = 2 * E; if (lim > 8192) lim = 8192;
        int nz = 0;
        const int* e32 = (const int*)ei;
        for (int i = 1 + 2 * tid; i < lim; i += 512) nz |= e32[i];
        #pragma unroll
        for (int off = 16; off > 0; off >>= 1)
            nz |= __shfl_xor_sync(0xffffffffu, nz, off);
        if (lane == 0) sSc[wid] = nz;
        __syncthreads();
        if (tid == 0) {
            int r = 0;
            #pragma unroll
            for (int w = 0; w < 8; w++) r |= sSc[w];
            sIs64 = (r == 0) ? 1 : 0;
        }
        __syncthreads();
    }
    const int is64 = sIs64;

    // histogram (d_deg zero at entry: static init call 1, re-zeroed phase D)
    for (int e = gtid; e < E; e += nthr) {
        int d = load_idx(ei, E + e, is64);
        if ((unsigned)d < (unsigned)N) atomicAdd(&d_deg[d], 1);
    }
    // gemm<0> (independent of CSR pipeline)
    gemm_phase<0>(x, nullptr, nullptr, Wx, d_h1, N, sWt);
    grid_barrier();                                            // B1

    // ---- Phase C: per-tile local scan + dinv; LAST block does mid-scan ----
    const int ntiles = (N + 255) / 256;
    for (int tile = blockIdx.x; tile < ntiles; tile += NB) {
        int i = tile * 256 + tid;
        int v = (i < N) ? d_deg[i] : 0;
        if (i < N) d_dinv[i] = rsqrtf((float)v + 1.0f);
        int xv = v;
        #pragma unroll
        for (int off = 1; off < 32; off <<= 1) {
            int y = __shfl_up_sync(0xffffffffu, xv, off);
            if (lane >= off) xv += y;
        }
        if (lane == 31) sSc[wid] = xv;
        __syncthreads();
        if (wid == 0 && lane < 8) {
            int s2 = sSc[lane];
            #pragma unroll
            for (int off = 1; off < 8; off <<= 1) {
                int y = __shfl_up_sync(0xffu, s2, off);
                if (lane >= off) s2 += y;
            }
            sSc[lane] = s2;
        }
        __syncthreads();
        int incl = xv + ((wid > 0) ? sSc[wid - 1] : 0);
        if (i < N) {
            int excl = incl - v;
            d_rowptr[i] = excl;                    // tile-local
            d_cursor[i] = excl;
        }
        if (tid == 255) d_bsum[tile] = incl;
        __syncthreads();
    }
    // last-block ticket -> mid-scan of tile totals
    {
        __shared__ int amLast;
        __threadfence();
        __syncthreads();
        if (tid == 0) {
            unsigned t = atomicAdd(&d_p2done, 1u);
            amLast = (t == (unsigned)(NB - 1));
            if (amLast) d_p2done = 0;
        }
        __syncthreads();
        if (amLast) {
            __threadfence();                       // acquire bsum writes
            int v = (tid < ntiles) ? d_bsum[tid] : 0;
            int xv = v;
            #pragma unroll
            for (int off = 1; off < 32; off <<= 1) {
                int y = __shfl_up_sync(0xffffffffu, xv, off);
                if (lane >= off) xv += y;
            }
            if (lane == 31) sSc[wid] = xv;
            __syncthreads();
            if (wid == 0 && lane < 8) {
                int s2 = sSc[lane];
                #pragma unroll
                for (int off = 1; off < 8; off <<= 1) {
                    int y = __shfl_up_sync(0xffu, s2, off);
                    if (lane >= off) s2 += y;
                }
                sSc[lane] = s2;
            }
            __syncthreads();
            int incl = xv + ((wid > 0) ? sSc[wid - 1] : 0);
            if (tid < ntiles) d_boff[tid] = incl - v;
        }
    }
    grid_barrier();                                            // B2

    // ---- Phase D: CSR fill (src premultiplied by C) + re-zero d_deg ----
    for (int e = gtid; e < E; e += nthr) {
        int s = load_idx(ei, e, is64);
        int d = load_idx(ei, E + e, is64);
        if ((unsigned)s < (unsigned)N && (unsigned)d < (unsigned)N) {
            int p = atomicAdd(&d_cursor[d], 1) + d_boff[d >> 8];
            d_csr[p] = make_int2(s * C, __float_as_int(d_dinv[s] * d_dinv[d]));
        }
    }
    for (int i = gtid; i < N; i += nthr) d_deg[i] = 0;
    grid_barrier();                                            // B3

    // ---- Phases E..I: agg0, gemm1, agg1, gemm2, agg2 ----
    agg_phase<0>(d_h1, bx, nullptr, nullptr, d_xgcn, N, sCS);
    grid_barrier();                                            // B4

    gemm_phase<1>(d_xgcn, h_prev, nullptr, Wuh, d_h1, N, sWt);
    grid_barrier();                                            // B5

    agg_phase<1>(d_h1, buh, nullptr, nullptr, d_g, N, sCS);
    grid_barrier();                                            // B6

    gemm_phase<2>(d_xgcn, h_prev, d_g, Wch, d_h1, N, sWt);
    grid_barrier();                                            // B7

    agg_phase<2>(d_h1, bch, d_g, h_prev, out, N, sCS);
}

// ---------------- launch: ONE kernel ----------------
extern "C" void kernel_launch(void* const* d_in, const int* in_sizes, int n_in,
                              void* d_out, int out_size)
{
    const float* x      = (const float*)d_in[0];
    const void*  ei     = d_in[1];
    const float* h_prev = (const float*)d_in[2];
    const float* Wx     = (const float*)d_in[3];
    const float* bx     = (const float*)d_in[4];
    const float* Wuh    = (const float*)d_in[5];
    const float* buh    = (const float*)d_in[6];
    const float* Wch    = (const float*)d_in[7];
    const float* bch    = (const float*)d_in[8];
    float*       out    = (float*)d_out;

    int N = in_sizes[0] / C;
    int E = in_sizes[1] / 2;
    if (N > NMAX) N = NMAX;
    if (E > EMAX) E = EMAX;

    const int SMEM_BYTES = SW_FLOATS * (int)sizeof(float) + 8 * 32 * (int)sizeof(int2);

    cudaFuncSetAttribute(mega_kernel,
                         cudaFuncAttributeMaxDynamicSharedMemorySize, SMEM_BYTES);

    int dev = 0;
    cudaGetDevice(&dev);
    int nsm = 148;
    cudaDeviceGetAttribute(&nsm, cudaDevAttrMultiProcessorCount, dev);
    int occ = 1;
    cudaOccupancyMaxActiveBlocksPerMultiprocessor(&occ, mega_kernel, 256, SMEM_BYTES);
    if (occ < 1) occ = 1;
    int grid = nsm * occ;   // guaranteed co-resident -> grid barrier is safe

    mega_kernel<<<grid, 256, SMEM_BYTES>>>(
        x, ei, h_prev, Wx, bx, Wuh, buh, Wch, bch, out, N, E);
}

// round 16
// speedup vs baseline: 1.3897x; 1.3897x over previous
#include <cuda_runtime.h>
#include <cstdint>

// ---------------- problem constants ----------------
#define C 96                 // feature channels (d = h = 96)
#define NMAX 65536
#define EMAX 1048576
#define WPAD 100             // padded k-stride for transposed W in smem
#define SW_FLOATS (C * WPAD) // 9600 floats = 38.4 KB

// ---------------- device scratch (no allocations allowed) ----------------
// NOTE: d_deg relies on static zero-init for the FIRST call; every call
// re-zeroes it during the fill phase for the next graph replay.
__device__ int   d_deg[NMAX];
__device__ int   d_rowptr[NMAX];       // tile-LOCAL exclusive scan
__device__ int   d_cursor[NMAX];       // tile-LOCAL fill cursor (post-fill: local end)
__device__ int   d_bsum[1024];         // per-tile degree totals
__device__ int   d_boff[1024];         // per-tile global offsets
__device__ int2  d_csr[EMAX];          // (src*C, weight-bits)
__device__ float d_dinv[NMAX];
__device__ float d_h1[(size_t)NMAX * C];
__device__ float d_xgcn[(size_t)NMAX * C];
__device__ float d_g[(size_t)NMAX * C];

// grid-barrier state (monotonic generation; survives across graph replays)
__device__ unsigned          d_barcnt = 0;
__device__ volatile unsigned d_bargen = 0;
__device__ unsigned          d_p2done = 0;   // last-block ticket for mid-scan

// ---------------- helpers ----------------
__device__ __forceinline__ float fsigmoid(float x) {
    return 1.0f / (1.0f + __expf(-x));
}
__device__ __forceinline__ float ftanh(float x) {
    return 1.0f - 2.0f / (__expf(2.0f * x) + 1.0f);
}
__device__ __forceinline__ int load_idx(const void* ei, int idx, int is64) {
    if (is64) return (int)((const long long*)ei)[idx];
    return ((const int*)ei)[idx];
}

__device__ __forceinline__ uint32_t f2tf32(float f) {
    uint32_t r;
    asm("cvt.rna.tf32.f32 %0, %1;" : "=r"(r) : "f"(f));
    return r;
}

// D += A(16x8 tf32) * B(8x8 tf32), fp32 accumulate. Row-major A, col-major B.
__device__ __forceinline__ void mma_tf32(
    float* c, uint32_t a0, uint32_t a1, uint32_t a2, uint32_t a3,
    uint32_t b0, uint32_t b1)
{
    asm volatile(
        "mma.sync.aligned.m16n8k8.row.col.f32.tf32.tf32.f32 "
        "{%0,%1,%2,%3}, {%4,%5,%6,%7}, {%8,%9}, {%0,%1,%2,%3};"
        : "+f"(c[0]), "+f"(c[1]), "+f"(c[2]), "+f"(c[3])
        : "r"(a0), "r"(a1), "r"(a2), "r"(a3), "r"(b0), "r"(b1));
}

// Software grid barrier (all blocks co-resident; grid sized via occupancy API).
__device__ __forceinline__ void grid_barrier() {
    __threadfence();
    __syncthreads();
    if (threadIdx.x == 0) {
        unsigned g = d_bargen;
        unsigned t = atomicAdd(&d_barcnt, 1u);
        if (t == gridDim.x - 1) {
            atomicExch(&d_barcnt, 0u);
            __threadfence();
            d_bargen = g + 1;
        } else {
            while (d_bargen == g) __nanosleep(64);
        }
    }
    __syncthreads();
    __threadfence();
}

// ---------------- GEMM phase (R14 config: 16x48 tile, measured best) ------
// out[N,96] = A[N,K] @ W[K,96]; K in 96-row segments. Per segment, W is
// tf32-rounded ONCE while staging into smem TRANSPOSED, pad stride 100
// (bank map (4n+k)%32 all-distinct -> conflict-free B-fragment loads).
// Single-MMA (no A compensation): measured rel_err 4.2e-5 (24x margin).
// Warp task = 16 rows x 48 cols (6 n-tiles, acc[6][4]=24 regs).
// Segment 1 accumulates via out +=.
template <int MODE>
__device__ void gemm_phase(
    const float* __restrict__ A0, const float* __restrict__ A1,
    const float* __restrict__ A2, const float* __restrict__ W,
    float* __restrict__ outp, int N, float* sWt)
{
    const int NSEG = (MODE == 0) ? 1 : 2;
    const int tid  = threadIdx.x;
    const int lane = tid & 31;
    const int wid  = tid >> 5;
    const int gwarp = blockIdx.x * 8 + wid;
    const int nwarp = gridDim.x * 8;
    const int rowtiles = (N + 15) >> 4;
    const int ntask = rowtiles * 2;          // x2 column halves

    const int lg = lane >> 2;                // 0..7
    const int kl = lane & 3;                 // 0..3

    for (int seg = 0; seg < NSEG; seg++) {
        __syncthreads();                      // prior users of sWt done
        const float* wseg = W + (size_t)seg * C * C;
        for (int i = tid; i < C * C; i += 256) {
            int k = i / C, n = i - k * C;     // i = k*96+n (coalesced gmem read)
            sWt[n * WPAD + k] = __uint_as_float(f2tf32(wseg[i]));
        }
        __syncthreads();

        const float* Asrc = (seg == 0) ? A0 : A1;

        for (int task = gwarp; task < ntask; task += nwarp) {
            const int rt   = task >> 1;
            const int half = task & 1;
            const int r0 = rt * 16 + lg;
            const int r1 = r0 + 8;
            const bool v0 = r0 < N;
            const bool v1 = r1 < N;
            const float* __restrict__ arow0 = Asrc + (size_t)r0 * C;
            const float* __restrict__ arow1 = Asrc + (size_t)r1 * C;

            float acc[6][4];
            #pragma unroll
            for (int nt = 0; nt < 6; nt++)
                #pragma unroll
                for (int q = 0; q < 4; q++) acc[nt][q] = 0.0f;

            #pragma unroll 2
            for (int ks = 0; ks < 12; ks++) {
                const int k0 = ks * 8;
                float a0 = v0 ? arow0[k0 + kl]     : 0.0f;
                float a1 = v1 ? arow1[k0 + kl]     : 0.0f;
                float a2 = v0 ? arow0[k0 + 4 + kl] : 0.0f;
                float a3 = v1 ? arow1[k0 + 4 + kl] : 0.0f;
                if (MODE == 2 && seg == 1) {
                    if (v0) {
                        a0 *= A2[(size_t)r0 * C + k0 + kl];
                        a2 *= A2[(size_t)r0 * C + k0 + 4 + kl];
                    }
                    if (v1) {
                        a1 *= A2[(size_t)r1 * C + k0 + kl];
                        a3 *= A2[(size_t)r1 * C + k0 + 4 + kl];
                    }
                }
                uint32_t h0 = f2tf32(a0), h1 = f2tf32(a1);
                uint32_t h2 = f2tf32(a2), h3 = f2tf32(a3);

                const float* wb = sWt + (size_t)(half * 48 + lg) * WPAD + k0 + kl;
                #pragma unroll
                for (int nt = 0; nt < 6; nt++) {
                    uint32_t b0 = __float_as_uint(wb[(size_t)nt * 8 * WPAD]);
                    uint32_t b1 = __float_as_uint(wb[(size_t)nt * 8 * WPAD + 4]);
                    mma_tf32(acc[nt], h0, h1, h2, h3, b0, b1);
                }
            }

            // store: d0,d1 -> (r0, cc..cc+1); d2,d3 -> (r1, cc..cc+1)
            const int cc = (lane & 3) * 2;
            #pragma unroll
            for (int nt = 0; nt < 6; nt++) {
                const int n0 = half * 48 + nt * 8 + cc;
                if (v0) {
                    float2* p = (float2*)(outp + (size_t)r0 * C + n0);
                    if (seg == 0) {
                        *p = make_float2(acc[nt][0], acc[nt][1]);
                    } else {
                        float2 o = *p;
                        *p = make_float2(o.x + acc[nt][0], o.y + acc[nt][1]);
                    }
                }
                if (v1) {
                    float2* p = (float2*)(outp + (size_t)r1 * C + n0);
                    if (seg == 0) {
                        *p = make_float2(acc[nt][2], acc[nt][3]);
                    } else {
                        float2 o = *p;
                        *p = make_float2(o.x + acc[nt][2], o.y + acc[nt][3]);
                    }
                }
            }
        }
    }
}

// ---------------- aggregation phase v2: warp-per-node ----------------
// One warp per node; lane owns channels {lane, lane+32, lane+64}.
// CSR edge stream staged ONCE per node (was 3x with warp-per-third);
// 8-edge unroll -> 24 independent gather LDGs in flight per warp.
// CSR stores src*C premultiplied. jbeg = local rowptr + tile offset;
// jend from post-fill cursor (== rowptr+deg).
template <int MODE>
__device__ void agg_phase(
    const float* __restrict__ H, const float* __restrict__ bias,
    const float* __restrict__ G, const float* __restrict__ HP,
    float* __restrict__ outp, int N, int2* sCS)
{
    const int wid  = threadIdx.x >> 5;
    const int lane = threadIdx.x & 31;
    int2* cs = &sCS[wid * 32];
    const int c0 = lane, c1 = lane + 32, c2 = lane + 64;

    for (int n = blockIdx.x * 8 + wid; n < N; n += gridDim.x * 8) {
        float dn = d_dinv[n];
        float sw = dn * dn;
        const float* hn = H + (size_t)n * C;
        float a0 = bias[c0] + sw * hn[c0];
        float a1 = bias[c1] + sw * hn[c1];
        float a2 = bias[c2] + sw * hn[c2];

        const int boff = d_boff[n >> 8];
        const int jbeg = d_rowptr[n] + boff;
        const int jend = d_cursor[n] + boff;

        for (int base = jbeg; base < jend; base += 32) {
            int cnt = jend - base;
            if (cnt > 32) cnt = 32;
            if (lane < cnt) cs[lane] = d_csr[base + lane];
            __syncwarp();
            int t = 0;
            for (; t + 8 <= cnt; t += 8) {
                float x0[8], x1[8], x2[8], wv[8];
                #pragma unroll
                for (int q = 0; q < 8; q++) {
                    int2 e = cs[t + q];
                    wv[q] = __int_as_float(e.y);
                    x0[q] = H[(size_t)(e.x + c0)];
                    x1[q] = H[(size_t)(e.x + c1)];
                    x2[q] = H[(size_t)(e.x + c2)];
                }
                #pragma unroll
                for (int q = 0; q < 8; q++) {
                    a0 += wv[q] * x0[q];
                    a1 += wv[q] * x1[q];
                    a2 += wv[q] * x2[q];
                }
            }
            for (; t < cnt; t++) {
                int2 e = cs[t];
                float w = __int_as_float(e.y);
                a0 += w * H[(size_t)(e.x + c0)];
                a1 += w * H[(size_t)(e.x + c1)];
                a2 += w * H[(size_t)(e.x + c2)];
            }
            __syncwarp();
        }

        const size_t o = (size_t)n * C;
        if (MODE == 0) {
            outp[o + c0] = a0; outp[o + c1] = a1; outp[o + c2] = a2;
        } else if (MODE == 1) {
            outp[o + c0] = fsigmoid(a0);
            outp[o + c1] = fsigmoid(a1);
            outp[o + c2] = fsigmoid(a2);
        } else {
            float u0 = G[o + c0], u1 = G[o + c1], u2 = G[o + c2];
            float p0 = HP[o + c0], p1 = HP[o + c1], p2 = HP[o + c2];
            outp[o + c0] = u0 * p0 + (1.0f - u0) * ftanh(a0);
            outp[o + c1] = u1 * p1 + (1.0f - u1) * ftanh(a1);
            outp[o + c2] = u2 * p2 + (1.0f - u2) * ftanh(a2);
        }
    }
}

// ---------------- the megakernel (7 grid barriers) ----------------
__global__ void __launch_bounds__(256, 4) mega_kernel(
    const float* __restrict__ x, const void* __restrict__ ei,
    const float* __restrict__ h_prev,
    const float* __restrict__ Wx,  const float* __restrict__ bx,
    const float* __restrict__ Wuh, const float* __restrict__ buh,
    const float* __restrict__ Wch, const float* __restrict__ bch,
    float* __restrict__ out, int N, int E)
{
    extern __shared__ float sWt[];                // [SW_FLOATS] (38.4 KB)
    int2* sCS = (int2*)(sWt + SW_FLOATS);         // [8*32] int2 (2 KB)
    int*  sSc = (int*)sCS;                        // scan scratch (aliased)
    __shared__ int sIs64;

    const int tid  = threadIdx.x;
    const int NB   = gridDim.x;
    const int gtid = blockIdx.x * 256 + tid;
    const int nthr = NB * 256;
    const int lane = tid & 31;
    const int wid  = tid >> 5;

    // ---- Phase A: block-local dtype detect + histogram + gemm<0> ----
    {
        int lim = 2 * E; if (lim > 8192) lim = 8192;
        int nz = 0;
        const int* e32 = (const int*)ei;
        for (int i = 1 + 2 * tid; i < lim; i += 512) nz |= e32[i];
        #pragma unroll
        for (int off = 16; off > 0; off >>= 1)
            nz |= __shfl_xor_sync(0xffffffffu, nz, off);
        if (lane == 0) sSc[wid] = nz;
        __syncthreads();
        if (tid == 0) {
            int r = 0;
            #pragma unroll
            for (int w = 0; w < 8; w++) r |= sSc[w];
            sIs64 = (r == 0) ? 1 : 0;
        }
        __syncthreads();
    }
    const int is64 = sIs64;

    // histogram (d_deg zero at entry: static init call 1, re-zeroed phase D)
    for (int e = gtid; e < E; e += nthr) {
        int d = load_idx(ei, E + e, is64);
        if ((unsigned)d < (unsigned)N) atomicAdd(&d_deg[d], 1);
    }
    // gemm<0> (independent of CSR pipeline)
    gemm_phase<0>(x, nullptr, nullptr, Wx, d_h1, N, sWt);
    grid_barrier();                                            // B1

    // ---- Phase C: per-tile local scan + dinv; LAST block does mid-scan ----
    const int ntiles = (N + 255) / 256;
    for (int tile = blockIdx.x; tile < ntiles; tile += NB) {
        int i = tile * 256 + tid;
        int v = (i < N) ? d_deg[i] : 0;
        if (i < N) d_dinv[i] = rsqrtf((float)v + 1.0f);
        int xv = v;
        #pragma unroll
        for (int off = 1; off < 32; off <<= 1) {
            int y = __shfl_up_sync(0xffffffffu, xv, off);
            if (lane >= off) xv += y;
        }
        if (lane == 31) sSc[wid] = xv;
        __syncthreads();
        if (wid == 0 && lane < 8) {
            int s2 = sSc[lane];
            #pragma unroll
            for (int off = 1; off < 8; off <<= 1) {
                int y = __shfl_up_sync(0xffu, s2, off);
                if (lane >= off) s2 += y;
            }
            sSc[lane] = s2;
        }
        __syncthreads();
        int incl = xv + ((wid > 0) ? sSc[wid - 1] : 0);
        if (i < N) {
            int excl = incl - v;
            d_rowptr[i] = excl;                    // tile-local
            d_cursor[i] = excl;
        }
        if (tid == 255) d_bsum[tile] = incl;
        __syncthreads();
    }
    // last-block ticket -> mid-scan of tile totals
    {
        __shared__ int amLast;
        __threadfence();
        __syncthreads();
        if (tid == 0) {
            unsigned t = atomicAdd(&d_p2done, 1u);
            amLast = (t == (unsigned)(NB - 1));
            if (amLast) d_p2done = 0;
        }
        __syncthreads();
        if (amLast) {
            __threadfence();                       // acquire bsum writes
            int v = (tid < ntiles) ? d_bsum[tid] : 0;
            int xv = v;
            #pragma unroll
            for (int off = 1; off < 32; off <<= 1) {
                int y = __shfl_up_sync(0xffffffffu, xv, off);
                if (lane >= off) xv += y;
            }
            if (lane == 31) sSc[wid] = xv;
            __syncthreads();
            if (wid == 0 && lane < 8) {
                int s2 = sSc[lane];
                #pragma unroll
                for (int off = 1; off < 8; off <<= 1) {
                    int y = __shfl_up_sync(0xffu, s2, off);
                    if (lane >= off) s2 += y;
                }
                sSc[lane] = s2;
            }
            __syncthreads();
            int incl = xv + ((wid > 0) ? sSc[wid - 1] : 0);
            if (tid < ntiles) d_boff[tid] = incl - v;
        }
    }
    grid_barrier();                                            // B2

    // ---- Phase D: CSR fill (src premultiplied by C) + re-zero d_deg ----
    for (int e = gtid; e < E; e += nthr) {
        int s = load_idx(ei, e, is64);
        int d = load_idx(ei, E + e, is64);
        if ((unsigned)s < (unsigned)N && (unsigned)d < (unsigned)N) {
            int p = atomicAdd(&d_cursor[d], 1) + d_boff[d >> 8];
            d_csr[p] = make_int2(s * C, __float_as_int(d_dinv[s] * d_dinv[d]));
        }
    }
    for (int i = gtid; i < N; i += nthr) d_deg[i] = 0;
    grid_barrier();                                            // B3

    // ---- Phases E..I: agg0, gemm1, agg1, gemm2, agg2 ----
    agg_phase<0>(d_h1, bx, nullptr, nullptr, d_xgcn, N, sCS);
    grid_barrier();                                            // B4

    gemm_phase<1>(d_xgcn, h_prev, nullptr, Wuh, d_h1, N, sWt);
    grid_barrier();                                            // B5

    agg_phase<1>(d_h1, buh, nullptr, nullptr, d_g, N, sCS);
    grid_barrier();                                            // B6

    gemm_phase<2>(d_xgcn, h_prev, d_g, Wch, d_h1, N, sWt);
    grid_barrier();                                            // B7

    agg_phase<2>(d_h1, bch, d_g, h_prev, out, N, sCS);
}

// ---------------- launch: ONE kernel ----------------
extern "C" void kernel_launch(void* const* d_in, const int* in_sizes, int n_in,
                              void* d_out, int out_size)
{
    const float* x      = (const float*)d_in[0];
    const void*  ei     = d_in[1];
    const float* h_prev = (const float*)d_in[2];
    const float* Wx     = (const float*)d_in[3];
    const float* bx     = (const float*)d_in[4];
    const float* Wuh    = (const float*)d_in[5];
    const float* buh    = (const float*)d_in[6];
    const float* Wch    = (const float*)d_in[7];
    const float* bch    = (const float*)d_in[8];
    float*       out    = (float*)d_out;

    int N = in_sizes[0] / C;
    int E = in_sizes[1] / 2;
    if (N > NMAX) N = NMAX;
    if (E > EMAX) E = EMAX;

    const int SMEM_BYTES = SW_FLOATS * (int)sizeof(float) + 8 * 32 * (int)sizeof(int2);

    cudaFuncSetAttribute(mega_kernel,
                         cudaFuncAttributeMaxDynamicSharedMemorySize, SMEM_BYTES);

    int dev = 0;
    cudaGetDevice(&dev);
    int nsm = 148;
    cudaDeviceGetAttribute(&nsm, cudaDevAttrMultiProcessorCount, dev);
    int occ = 1;
    cudaOccupancyMaxActiveBlocksPerMultiprocessor(&occ, mega_kernel, 256, SMEM_BYTES);
    if (occ < 1) occ = 1;
    int grid = nsm * occ;   // guaranteed co-resident -> grid barrier is safe

    mega_kernel<<<grid, 256, SMEM_BYTES>>>(
        x, ei, h_prev, Wx, bx, Wuh, buh, Wch, bch, out, N, E);
}